// round 11
// baseline (speedup 1.0000x reference)
#include <cuda_runtime.h>
#include <math.h>

#define HW    80
#define NPIX  6400          // 80*80
#define NPAIR 32            // B*L*L
#define NIMG  8             // B*L

typedef unsigned long long ull;

// ---------------- scratch (static __device__, no allocations) ----------------
__device__ float g_minv[NPAIR * 6];
__device__ float g_mask[NPAIR * NPIX];
__device__ float g_masksum[NIMG * NPIX];
__device__ float g_y[NIMG * 64 * NPIX];        // ping
__device__ float g_y2[NIMG * 64 * NPIX];       // pong
__device__ float g_convn[NPAIR * 64 * NPIX];   // conv(neighbor)
__device__ float g_ego[NIMG * 64 * NPIX];      // conv(ego)+bias
__device__ float2 g_wnbr2[32 * 64 * 9];        // [co2][cin][tap] cout-paired
__device__ float2 g_wego2[32 * 64 * 9];
__device__ float2 g_wgru2[64 * 128 * 9];       // [(upd,cand) pair][ci][tap]
__device__ float2 g_bgru2[64];                 // (gates_b[64+j], can_b[j])

// ---------------- packed fp32x2 helpers (sm_103a FFMA2) ----------------
__device__ __forceinline__ void fma2(ull& d, ull a, ull b) {
    asm("fma.rn.f32x2 %0, %1, %2, %0;" : "+l"(d) : "l"(a), "l"(b));
}
__device__ __forceinline__ ull bcast2(float v) {
    ull r;
    asm("mov.b64 %0, {%1, %1};" : "=l"(r) : "f"(v));
    return r;
}
__device__ __forceinline__ float2 unpack2(ull v) {
    float2 f;
    asm("mov.b64 {%0, %1}, %2;" : "=f"(f.x), "=f"(f.y) : "l"(v));
    return f;
}

// accurate activations (avoid fast-math tanh.approx)
__device__ __forceinline__ float sigmoid_acc(float u) {
    return 1.0f / (1.0f + expf(-u));
}
__device__ __forceinline__ float tanh_acc(float x) {
    float a = fabsf(x);
    float e = expf(-2.0f * a);
    float t = (1.0f - e) / (1.0f + e);
    return copysignf(t, x);
}

// ---------------- affine inverse: replicate reference fp32 arithmetic -------
__global__ void k_minv(const float* __restrict__ P) {
    int p = threadIdx.x;
    if (p >= NPAIR) return;
    const float* M = P + p * 16;
    float a = M[0], b = M[1];
    float c = M[4], d = M[5];
    float txs = __fdiv_rn(M[3], 0.8f);
    float tys = __fdiv_rn(M[7], 0.8f);
    const float cx = 40.0f, cy = 40.0f;
    float dot0 = __fadd_rn(__fmul_rn(a, cx), __fmul_rn(b, cy));
    float dot1 = __fadd_rn(__fmul_rn(c, cx), __fmul_rn(d, cy));
    float Tx = __fadd_rn(__fsub_rn(cx, dot0), txs);
    float Ty = __fadd_rn(__fsub_rn(cy, dot1), tys);

    float ra  = __fdiv_rn(1.0f, a);
    float l10 = __fmul_rn(c, ra);
    float u22 = __fmaf_rn(-l10, b, d);
    float u23 = __fmaf_rn(-l10, Tx, Ty);

    float x1_0 = __fdiv_rn(-l10, u22);
    float x0_0 = __fdiv_rn(__fmaf_rn(-b, x1_0, 1.0f), a);
    float x1_1 = __fdiv_rn(1.0f, u22);
    float x0_1 = __fdiv_rn(__fmul_rn(-b, x1_1), a);
    float x1_2 = __fdiv_rn(-u23, u22);
    float x0_2 = __fdiv_rn(__fmaf_rn(-b, x1_2, -Tx), a);

    float* o = g_minv + p * 6;
    o[0] = x0_0; o[1] = x0_1; o[2] = x0_2;
    o[3] = x1_0; o[4] = x1_1; o[5] = x1_2;
}

__device__ __forceinline__ float coordx(const float* mv, float x, float y) {
    float s = __fmul_rn(mv[0], x);
    s = __fmaf_rn(mv[1], y, s);
    return __fadd_rn(s, mv[2]);
}
__device__ __forceinline__ float coordy(const float* mv, float x, float y) {
    float s = __fmul_rn(mv[3], x);
    s = __fmaf_rn(mv[4], y, s);
    return __fadd_rn(s, mv[5]);
}

// ---------------- masks + masksum fused ----------------
__global__ void k_maskall() {
    int bj = blockIdx.y;                 // b*4 + j
    int p = blockIdx.x * 256 + threadIdx.x;
    if (p >= NPIX) return;
    int b = bj >> 2, j = bj & 3;
    float x = (float)(p % HW), y = (float)(p / HW);
    float s = 0.0f;
#pragma unroll
    for (int i = 0; i < 4; i++) {
        int pair = (b * 4 + i) * 4 + j;
        const float* mv = g_minv + pair * 6;
        float sx = coordx(mv, x, y);
        float sy = coordy(mv, x, y);
        int ix = (int)rintf(sx);
        int iy = (int)rintf(sy);
        float m = (ix >= 0 && ix < HW && iy >= 0 && iy < HW) ? 1.0f : 0.0f;
        g_mask[pair * NPIX + p] = m;
        s += m;
    }
    g_masksum[bj * NPIX + p] = s;
}

// ---------------- initial transform: y[c,h,w] = x[c, 79-w, h] ----------------
__global__ void k_transform(const float* __restrict__ x) {
    int idx = blockIdx.x * 256 + threadIdx.x;
    int p = idx % NPIX;
    int c = (idx / NPIX) & 63;
    int bl = idx / (NPIX * 64);
    int h = p / HW, w = p % HW;
    g_y[idx] = x[(bl * 64 + c) * NPIX + (HW - 1 - w) * HW + h];
}

// ======== fused tiled direct 3x3 conv (SAME), NCHW fp32, FFMA2 ========
// 16x8 tile, 128 thr, 4 blocks/SM, DOUBLE-BUFFERED staging (ping-pong smem).
// Inner loop identical to R10 (288 FFMA2 : ~108 other per ci-slice).
// MODE 0: z<32 -> NBR (bilinear-warp staging, mask skip) ; z>=32 -> EGO(+msg_b)
// MODE 2: GRU (ci<64 y, ci>=64 masked-mean agg on the fly; (upd,cand) lanes;
//         epilogue sigmoid*tanh -> ydst)
// dyn smem (floats): sX 2x1600 | sW2 2x2304 f2 (=9216 f) | aux 1440  = 13856
#define SMEM_FLOATS 13856

template <int MODE, int CIN>
__global__ __launch_bounds__(128, 4)
void conv_all(const float* __restrict__ ysrc,
              const float* __restrict__ convn,
              const float* __restrict__ ego,
              const float2* __restrict__ Wnbr,
              const float2* __restrict__ Wego,
              const float* __restrict__ msgb,
              const float2* __restrict__ bgru2,
              float* __restrict__ convn_out,
              float* __restrict__ ego_out,
              float* __restrict__ ydst) {
    extern __shared__ float sm[];
    float*  sXb = sm;                         // [2][8][10][20]
    float2* sWb = (float2*)(sm + 3200);       // [2][32*72]
    float4* aw  = (float4*)(sm + 12416);      // MODE0: 180 float4
    int4*   aiv = (int4*)(sm + 12416 + 720);  // MODE0: 180 int4
    float*  amk = sm + 12416;                 // MODE2: 180*5 floats

    const int z = blockIdx.z;
    const bool isNbr = (MODE == 0) && (z < 32);
    const int img = (MODE == 0) ? (isNbr ? z : z - 32) : z;
    const int tx = blockIdx.x % 5, ty = blockIdx.x / 5;
    const int w0 = tx * 16, h0 = ty * 8;
    const int t = threadIdx.x;
    const int s = t & 31;
    const int wl = s & 15;           // col in tile
    const int hq = s >> 4;           // 0..1 -> rows hq*4..hq*4+3
    const int cg = t >> 5;           // 0..3 cout group (8 pairs each)

    const float* srcI = nullptr;
    const float2* Wt2;
    if (MODE == 0) {
        if (isNbr) {
            const float* mp = g_mask + (long)img * NPIX;
            int any = (mp[(h0 + (t >> 4)) * HW + (w0 + (t & 15))] != 0.0f);
            if (__syncthreads_count(any) == 0) return;
            int b = img >> 4, i = (img >> 2) & 3;
            srcI = ysrc + (long)(b * 4 + i) * 64 * NPIX;
            const float* mv = g_minv + img * 6;
            for (int idx = t; idx < 180; idx += 128) {
                int r = idx / 18, c = idx % 18;
                int gh = h0 - 1 + r, gw = w0 - 1 + c;
                float4 wv = make_float4(0.f, 0.f, 0.f, 0.f);
                int4 iv = make_int4(0, 0, 0, 0);
                if (gh >= 0 && gh < HW && gw >= 0 && gw < HW) {
                    float X = (float)gw, Y = (float)gh;
                    float sx = coordx(mv, X, Y);
                    float sy = coordy(mv, X, Y);
                    float x0f = floorf(sx), y0f = floorf(sy);
                    float fx = __fsub_rn(sx, x0f), fy = __fsub_rn(sy, y0f);
                    int x0 = (int)x0f, y0 = (int)y0f;
                    int x1 = x0 + 1, y1 = y0 + 1;
                    int cx0 = min(max(x0, 0), HW - 1), cx1 = min(max(x1, 0), HW - 1);
                    int cy0 = min(max(y0, 0), HW - 1), cy1 = min(max(y1, 0), HW - 1);
                    float vx0 = (x0 >= 0 && x0 < HW) ? 1.0f : 0.0f;
                    float vx1 = (x1 >= 0 && x1 < HW) ? 1.0f : 0.0f;
                    float vy0 = (y0 >= 0 && y0 < HW) ? 1.0f : 0.0f;
                    float vy1 = (y1 >= 0 && y1 < HW) ? 1.0f : 0.0f;
                    float gx = __fsub_rn(1.0f, fx), gy = __fsub_rn(1.0f, fy);
                    wv.x = __fmul_rn(__fmul_rn(vx0, vy0), __fmul_rn(gx, gy));
                    wv.y = __fmul_rn(__fmul_rn(vx1, vy0), __fmul_rn(fx, gy));
                    wv.z = __fmul_rn(__fmul_rn(vx0, vy1), __fmul_rn(gx, fy));
                    wv.w = __fmul_rn(__fmul_rn(vx1, vy1), __fmul_rn(fx, fy));
                    iv.x = cy0 * HW + cx0; iv.y = cy0 * HW + cx1;
                    iv.z = cy1 * HW + cx0; iv.w = cy1 * HW + cx1;
                }
                aw[idx] = wv;
                aiv[idx] = iv;
            }
            Wt2 = Wnbr;
        } else {
            srcI = ysrc + (long)img * 64 * NPIX;
            Wt2 = Wego;
        }
    } else {
        srcI = ysrc + (long)img * 64 * NPIX;
        Wt2 = Wnbr;                  // carries gru weights in MODE2 call
        int b = img >> 2, j = img & 3;
        for (int idx = t; idx < 180; idx += 128) {
            int r = idx / 18, c = idx % 18;
            int gh = h0 - 1 + r, gw = w0 - 1 + c;
            float ms = 0.f, m0 = 0.f, m1 = 0.f, m2 = 0.f, m3 = 0.f;
            if (gh >= 0 && gh < HW && gw >= 0 && gw < HW) {
                int p = gh * HW + gw;
                ms = g_masksum[img * NPIX + p];
                m0 = g_mask[((b * 4 + 0) * 4 + j) * NPIX + p];
                m1 = g_mask[((b * 4 + 1) * 4 + j) * NPIX + p];
                m2 = g_mask[((b * 4 + 2) * 4 + j) * NPIX + p];
                m3 = g_mask[((b * 4 + 3) * 4 + j) * NPIX + p];
            }
            amk[idx * 5 + 0] = ms; amk[idx * 5 + 1] = m0;
            amk[idx * 5 + 2] = m1; amk[idx * 5 + 3] = m2;
            amk[idx * 5 + 4] = m3;
        }
    }
    __syncthreads();   // aux ready (and uniform across block)

    // ---- staging helper: stage ci-slice cin0 into buffer buf ----
    auto stage = [&](int cin0, int buf) {
        float* sX = sXb + buf * 1600;          // [ci][10][20]
        float2* sW2 = sWb + buf * 2304;
        for (int idx = t; idx < 8 * 180; idx += 128) {
            int ci = idx / 180, rem = idx % 180;
            int r = rem / 18, c = rem % 18;
            float v = 0.0f;
            if (MODE == 0 && isNbr) {
                float4 wv = aw[rem];
                int4 iv = aiv[rem];
                const float* sc = srcI + (cin0 + ci) * NPIX;
                v = __fmul_rn(wv.x, sc[iv.x]);
                v = __fadd_rn(v, __fmul_rn(wv.y, sc[iv.y]));
                v = __fadd_rn(v, __fmul_rn(wv.z, sc[iv.z]));
                v = __fadd_rn(v, __fmul_rn(wv.w, sc[iv.w]));
            } else {
                int gh = h0 - 1 + r, gw = w0 - 1 + c;
                if (gh >= 0 && gh < HW && gw >= 0 && gw < HW) {
                    int p = gh * HW + gw;
                    if (MODE == 0 || cin0 < 64) {
                        v = srcI[(cin0 + ci) * NPIX + p];
                    } else {
                        int cb = cin0 - 64 + ci;
                        int b = img >> 2, j = img & 3;
                        v = __fmul_rn(amk[rem * 5 + 0],
                                      ego[((long)img * 64 + cb) * NPIX + p]);
                        v = __fmaf_rn(amk[rem * 5 + 1],
                                      convn[((long)((b * 4 + 0) * 4 + j) * 64 + cb) * NPIX + p], v);
                        v = __fmaf_rn(amk[rem * 5 + 2],
                                      convn[((long)((b * 4 + 1) * 4 + j) * 64 + cb) * NPIX + p], v);
                        v = __fmaf_rn(amk[rem * 5 + 3],
                                      convn[((long)((b * 4 + 2) * 4 + j) * 64 + cb) * NPIX + p], v);
                        v = __fmaf_rn(amk[rem * 5 + 4],
                                      convn[((long)((b * 4 + 3) * 4 + j) * 64 + cb) * NPIX + p], v);
                        v = __fmul_rn(0.25f, v);
                    }
                }
            }
            sX[ci * 200 + r * 20 + c] = v;
        }
        for (int idx = t; idx < 32 * 72; idx += 128) {
            int co2 = idx / 72, rem = idx % 72;
            sW2[co2 * 72 + rem] =
                Wt2[((blockIdx.y * 32 + co2) * CIN + cin0) * 9 + rem];
        }
    };

    ull acc2[4][8];
#pragma unroll
    for (int k = 0; k < 4; k++)
#pragma unroll
        for (int j = 0; j < 8; j++) acc2[k][j] = 0ULL;

    const int NS = CIN / 8;
    stage(0, 0);
    __syncthreads();
#pragma unroll 1
    for (int sl = 0; sl < NS; sl++) {
        if (sl + 1 < NS) stage((sl + 1) * 8, (sl + 1) & 1);
        const float* sX = sXb + (sl & 1) * 1600;
        const float2* sW2 = sWb + (sl & 1) * 2304;
#pragma unroll 1
        for (int ci = 0; ci < 8; ci++) {
            ull xb[6][3];
#pragma unroll
            for (int rr = 0; rr < 6; rr++)
#pragma unroll
                for (int cc = 0; cc < 3; cc++)
                    xb[rr][cc] = bcast2(sX[ci * 200 + (hq * 4 + rr) * 20 + wl + cc]);
            const float2* wp = &sW2[(cg * 8) * 72 + ci * 9];
#pragma unroll
            for (int j = 0; j < 8; j++) {
#pragma unroll
                for (int tap = 0; tap < 9; tap++) {
                    ull w2 = *reinterpret_cast<const ull*>(&wp[j * 72 + tap]);
                    int r = tap / 3, c = tap % 3;
                    fma2(acc2[0][j], xb[0 + r][c], w2);
                    fma2(acc2[1][j], xb[1 + r][c], w2);
                    fma2(acc2[2][j], xb[2 + r][c], w2);
                    fma2(acc2[3][j], xb[3 + r][c], w2);
                }
            }
        }
        __syncthreads();
    }
    // ---- epilogue ----
    if (MODE == 2) {
#pragma unroll
        for (int j = 0; j < 8; j++) {
            int pr = blockIdx.y * 32 + cg * 8 + j;
            float2 bb = bgru2[pr];
#pragma unroll
            for (int k = 0; k < 4; k++) {
                int h = h0 + hq * 4 + k, w = w0 + wl;
                float2 f = unpack2(acc2[k][j]);
                ydst[((long)img * 64 + pr) * NPIX + h * HW + w] =
                    sigmoid_acc(f.x + bb.x) * tanh_acc(f.y + bb.y);
            }
        }
    } else {
        float* outp = isNbr ? (convn_out + (long)img * 64 * NPIX)
                            : (ego_out + (long)img * 64 * NPIX);
#pragma unroll
        for (int j = 0; j < 8; j++) {
            int co = (cg * 8 + j) * 2;
            float bv0 = isNbr ? 0.0f : msgb[co];
            float bv1 = isNbr ? 0.0f : msgb[co + 1];
#pragma unroll
            for (int k = 0; k < 4; k++) {
                int h = h0 + hq * 4 + k, w = w0 + wl;
                float2 f = unpack2(acc2[k][j]);
                outp[(long)co * NPIX + h * HW + w] = f.x + bv0;
                outp[(long)(co + 1) * NPIX + h * HW + w] = f.y + bv1;
            }
        }
    }
}

// ---------------- weight prepack ----------------
__global__ void k_prepack(const float* __restrict__ msg_w,
                          const float* __restrict__ gates_w,
                          const float* __restrict__ gates_b,
                          const float* __restrict__ can_w,
                          const float* __restrict__ can_b) {
    int idx = blockIdx.x * 256 + threadIdx.x;
    if (idx < 18432) {                         // msg split: [co2][ci<64][9]
        int co2 = idx / 576, rem = idx % 576;
        int coA = 2 * co2, coB = 2 * co2 + 1;
        g_wnbr2[idx] = make_float2(msg_w[coA * 1152 + rem],
                                   msg_w[coB * 1152 + rem]);
        g_wego2[idx] = make_float2(msg_w[coA * 1152 + 576 + rem],
                                   msg_w[coB * 1152 + 576 + rem]);
        return;
    }
    int k = idx - 18432;
    if (k < 73728) {                           // gru (update,cand) lane pairs
        int pr = k / 1152, rem = k % 1152;
        g_wgru2[k] = make_float2(gates_w[(64 + pr) * 1728 + rem],
                                 can_w[pr * 1728 + rem]);
        return;
    }
    k -= 73728;
    if (k < 64)
        g_bgru2[k] = make_float2(gates_b[64 + k], can_b[k]);
}

// ---------------- output: out[b,h,w,o] = mlp_w[o,:]·h1[b,0,:,w,79-h]+mlp_b ----
__global__ void k_out(const float* __restrict__ mlp_w,
                      const float* __restrict__ mlp_b,
                      const float* __restrict__ yfin,
                      float* __restrict__ out) {
    __shared__ float sW[64 * 65];
    __shared__ float sx[4][64];
    int t = threadIdx.x;
    for (int idx = t; idx < 4096; idx += 256) {
        int o = idx >> 6, c = idx & 63;
        sW[c * 65 + o] = mlp_w[idx];
    }
    int pix = t >> 6, o = t & 63;
    int pp = blockIdx.x * 4 + pix;
    int b = pp / NPIX, pr = pp % NPIX;
    int h = pr / HW, w = pr % HW;
    int q = w * HW + (HW - 1 - h);
    sx[pix][o] = yfin[(b * 4) * 64 * NPIX + o * NPIX + q];
    __syncthreads();
    float acc = mlp_b[o];
#pragma unroll 8
    for (int c = 0; c < 64; c++)
        acc = fmaf(sx[pix][c], sW[c * 65 + o], acc);
    out[pp * 64 + o] = acc;
}

// ---------------- host orchestration ----------------
extern "C" void kernel_launch(void* const* d_in, const int* in_sizes, int n_in,
                              void* d_out, int out_size) {
    const float* x       = (const float*)d_in[0];
    const float* pt      = (const float*)d_in[2];
    const float* msg_w   = (const float*)d_in[4];
    const float* msg_b   = (const float*)d_in[5];
    const float* gates_w = (const float*)d_in[6];
    const float* gates_b = (const float*)d_in[7];
    const float* can_w   = (const float*)d_in[8];
    const float* can_b   = (const float*)d_in[9];
    const float* mlp_w   = (const float*)d_in[10];
    const float* mlp_b   = (const float*)d_in[11];

    float *p_y, *p_y2, *p_convn, *p_ego;
    float2 *p_wnbr2, *p_wego2, *p_wgru2, *p_bgru2;
    cudaGetSymbolAddress((void**)&p_y, g_y);
    cudaGetSymbolAddress((void**)&p_y2, g_y2);
    cudaGetSymbolAddress((void**)&p_convn, g_convn);
    cudaGetSymbolAddress((void**)&p_ego, g_ego);
    cudaGetSymbolAddress((void**)&p_wnbr2, g_wnbr2);
    cudaGetSymbolAddress((void**)&p_wego2, g_wego2);
    cudaGetSymbolAddress((void**)&p_wgru2, g_wgru2);
    cudaGetSymbolAddress((void**)&p_bgru2, g_bgru2);

    const int smemB = SMEM_FLOATS * 4;   // 55424 B dynamic shared
    cudaFuncSetAttribute(conv_all<0, 64>,
                         cudaFuncAttributeMaxDynamicSharedMemorySize, smemB);
    cudaFuncSetAttribute(conv_all<2, 128>,
                         cudaFuncAttributeMaxDynamicSharedMemorySize, smemB);

    k_minv<<<1, 32>>>(pt);
    k_prepack<<<(18432 + 73728 + 64 + 255) / 256, 256>>>(msg_w, gates_w,
                                                         gates_b, can_w, can_b);
    k_maskall<<<dim3(25, NIMG), 256>>>();
    k_transform<<<(NIMG * 64 * NPIX) / 256, 256>>>(x);

    for (int it = 0; it < 2; it++) {
        const float* ysrc = (it == 0) ? p_y : p_y2;
        float* ydst       = (it == 0) ? p_y2 : p_y;
        // merged NBR(32 pairs) + EGO(8 imgs): 2000 blocks of 128 thr
        conv_all<0, 64><<<dim3(50, 1, 40), 128, smemB>>>(
            ysrc, nullptr, nullptr, p_wnbr2, p_wego2, msg_b, nullptr,
            p_convn, p_ego, nullptr);
        // GRU conv with fused agg + pointwise: 800 blocks of 128 thr
        conv_all<2, 128><<<dim3(50, 2, NIMG), 128, smemB>>>(
            ysrc, p_convn, p_ego, p_wgru2, nullptr, nullptr, p_bgru2,
            nullptr, nullptr, ydst);
    }

    k_out<<<2 * NPIX / 4, 256>>>(mlp_w, mlp_b, p_y, (float*)d_out);
}

// round 12
// speedup vs baseline: 1.0630x; 1.0630x over previous
#include <cuda_runtime.h>
#include <math.h>

#define HW    80
#define NPIX  6400          // 80*80
#define NPAIR 32            // B*L*L
#define NIMG  8             // B*L

typedef unsigned long long ull;

// ---------------- scratch (static __device__, no allocations) ----------------
__device__ float g_minv[NPAIR * 6];
__device__ float g_mask[NPAIR * NPIX];
__device__ float g_masksum[NIMG * NPIX];
__device__ float g_y[NIMG * 64 * NPIX];        // ping
__device__ float g_y2[NIMG * 64 * NPIX];       // pong
__device__ float g_nbr[NPAIR * 64 * NPIX];     // warped neighbors
__device__ float g_convn[NPAIR * 64 * NPIX];   // conv(neighbor)
__device__ float g_ego[NIMG * 64 * NPIX];      // conv(ego)+bias
__device__ float g_agg[NIMG * 64 * NPIX];      // masked mean
__device__ float2 g_wnbr2[32 * 64 * 9];        // [co2][cin][tap] cout-paired
__device__ float2 g_wego2[32 * 64 * 9];
__device__ float2 g_wgru2[64 * 128 * 9];       // [(upd,cand) pair][ci][tap]
__device__ float2 g_bgru2[64];                 // (gates_b[64+j], can_b[j])

// ---------------- packed fp32x2 helpers (sm_103a FFMA2) ----------------
__device__ __forceinline__ void fma2(ull& d, ull a, ull b) {
    asm("fma.rn.f32x2 %0, %1, %2, %0;" : "+l"(d) : "l"(a), "l"(b));
}
__device__ __forceinline__ ull bcast2(float v) {
    ull r;
    asm("mov.b64 %0, {%1, %1};" : "=l"(r) : "f"(v));
    return r;
}
__device__ __forceinline__ float2 unpack2(ull v) {
    float2 f;
    asm("mov.b64 {%0, %1}, %2;" : "=f"(f.x), "=f"(f.y) : "l"(v));
    return f;
}

// accurate activations (avoid fast-math tanh.approx)
__device__ __forceinline__ float sigmoid_acc(float u) {
    return 1.0f / (1.0f + expf(-u));
}
__device__ __forceinline__ float tanh_acc(float x) {
    float a = fabsf(x);
    float e = expf(-2.0f * a);
    float t = (1.0f - e) / (1.0f + e);
    return copysignf(t, x);
}

// ---------------- affine inverse: replicate reference fp32 arithmetic -------
__global__ void k_minv(const float* __restrict__ P) {
    int p = threadIdx.x;
    if (p >= NPAIR) return;
    const float* M = P + p * 16;
    float a = M[0], b = M[1];
    float c = M[4], d = M[5];
    float txs = __fdiv_rn(M[3], 0.8f);
    float tys = __fdiv_rn(M[7], 0.8f);
    const float cx = 40.0f, cy = 40.0f;
    float dot0 = __fadd_rn(__fmul_rn(a, cx), __fmul_rn(b, cy));
    float dot1 = __fadd_rn(__fmul_rn(c, cx), __fmul_rn(d, cy));
    float Tx = __fadd_rn(__fsub_rn(cx, dot0), txs);
    float Ty = __fadd_rn(__fsub_rn(cy, dot1), tys);

    float ra  = __fdiv_rn(1.0f, a);
    float l10 = __fmul_rn(c, ra);
    float u22 = __fmaf_rn(-l10, b, d);
    float u23 = __fmaf_rn(-l10, Tx, Ty);

    float x1_0 = __fdiv_rn(-l10, u22);
    float x0_0 = __fdiv_rn(__fmaf_rn(-b, x1_0, 1.0f), a);
    float x1_1 = __fdiv_rn(1.0f, u22);
    float x0_1 = __fdiv_rn(__fmul_rn(-b, x1_1), a);
    float x1_2 = __fdiv_rn(-u23, u22);
    float x0_2 = __fdiv_rn(__fmaf_rn(-b, x1_2, -Tx), a);

    float* o = g_minv + p * 6;
    o[0] = x0_0; o[1] = x0_1; o[2] = x0_2;
    o[3] = x1_0; o[4] = x1_1; o[5] = x1_2;
}

__device__ __forceinline__ float coordx(const float* mv, float x, float y) {
    float s = __fmul_rn(mv[0], x);
    s = __fmaf_rn(mv[1], y, s);
    return __fadd_rn(s, mv[2]);
}
__device__ __forceinline__ float coordy(const float* mv, float x, float y) {
    float s = __fmul_rn(mv[3], x);
    s = __fmaf_rn(mv[4], y, s);
    return __fadd_rn(s, mv[5]);
}

// ---------------- masks + masksum fused ----------------
__global__ void k_maskall() {
    int bj = blockIdx.y;                 // b*4 + j
    int p = blockIdx.x * 256 + threadIdx.x;
    if (p >= NPIX) return;
    int b = bj >> 2, j = bj & 3;
    float x = (float)(p % HW), y = (float)(p / HW);
    float s = 0.0f;
#pragma unroll
    for (int i = 0; i < 4; i++) {
        int pair = (b * 4 + i) * 4 + j;
        const float* mv = g_minv + pair * 6;
        float sx = coordx(mv, x, y);
        float sy = coordy(mv, x, y);
        int ix = (int)rintf(sx);
        int iy = (int)rintf(sy);
        float m = (ix >= 0 && ix < HW && iy >= 0 && iy < HW) ? 1.0f : 0.0f;
        g_mask[pair * NPIX + p] = m;
        s += m;
    }
    g_masksum[bj * NPIX + p] = s;
}

// ---------------- initial transform: y[c,h,w] = x[c, 79-w, h] ----------------
__global__ void k_transform(const float* __restrict__ x) {
    int idx = blockIdx.x * 256 + threadIdx.x;
    int p = idx % NPIX;
    int c = (idx / NPIX) & 63;
    int bl = idx / (NPIX * 64);
    int h = p / HW, w = p % HW;
    g_y[idx] = x[(bl * 64 + c) * NPIX + (HW - 1 - w) * HW + h];
}

// ---------------- bilinear warp of y[b,i] by T[pair] (HBM-bound) ------------
__global__ void k_warp(const float* __restrict__ ysrc) {
    int pair = blockIdx.y;
    int p = blockIdx.x * 256 + threadIdx.x;
    if (p >= NPIX) return;
    int b = pair >> 4;
    int i = (pair >> 2) & 3;
    const float* mv = g_minv + pair * 6;
    float x = (float)(p % HW), y = (float)(p / HW);
    float sx = coordx(mv, x, y);
    float sy = coordy(mv, x, y);
    float x0f = floorf(sx), y0f = floorf(sy);
    float fx = __fsub_rn(sx, x0f), fy = __fsub_rn(sy, y0f);
    int x0 = (int)x0f, y0 = (int)y0f;
    int x1 = x0 + 1, y1 = y0 + 1;
    int cx0 = min(max(x0, 0), HW - 1), cx1 = min(max(x1, 0), HW - 1);
    int cy0 = min(max(y0, 0), HW - 1), cy1 = min(max(y1, 0), HW - 1);
    float vx0 = (x0 >= 0 && x0 < HW) ? 1.0f : 0.0f;
    float vx1 = (x1 >= 0 && x1 < HW) ? 1.0f : 0.0f;
    float vy0 = (y0 >= 0 && y0 < HW) ? 1.0f : 0.0f;
    float vy1 = (y1 >= 0 && y1 < HW) ? 1.0f : 0.0f;
    float gx = __fsub_rn(1.0f, fx), gy = __fsub_rn(1.0f, fy);
    float w00 = __fmul_rn(__fmul_rn(vx0, vy0), __fmul_rn(gx, gy));
    float w10 = __fmul_rn(__fmul_rn(vx1, vy0), __fmul_rn(fx, gy));
    float w01 = __fmul_rn(__fmul_rn(vx0, vy1), __fmul_rn(gx, fy));
    float w11 = __fmul_rn(__fmul_rn(vx1, vy1), __fmul_rn(fx, fy));
    int i00 = cy0 * HW + cx0, i10 = cy0 * HW + cx1;
    int i01 = cy1 * HW + cx0, i11 = cy1 * HW + cx1;
    const float* src = ysrc + (long)(b * 4 + i) * 64 * NPIX;
    float* dst = g_nbr + (long)pair * 64 * NPIX;
#pragma unroll 4
    for (int c = 0; c < 64; c++) {
        const float* sc = src + c * NPIX;
        float v = __fmul_rn(w00, sc[i00]);
        v = __fadd_rn(v, __fmul_rn(w10, sc[i10]));
        v = __fadd_rn(v, __fmul_rn(w01, sc[i01]));
        v = __fadd_rn(v, __fmul_rn(w11, sc[i11]));
        dst[c * NPIX + p] = v;
    }
}

// ---------------- masked mean over i (HBM-bound) ----------------
__global__ void k_agg() {
    int bj = blockIdx.y;
    int p = blockIdx.x * 256 + threadIdx.x;
    if (p >= NPIX) return;
    int b = bj >> 2, j = bj & 3;
    float ms = g_masksum[bj * NPIX + p];
    float m[4];
#pragma unroll
    for (int i = 0; i < 4; i++)
        m[i] = g_mask[((b * 4 + i) * 4 + j) * NPIX + p];
#pragma unroll 4
    for (int c = 0; c < 64; c++) {
        float v = __fmul_rn(ms, g_ego[((long)bj * 64 + c) * NPIX + p]);
        v = __fmaf_rn(m[0], g_convn[((long)((b * 4 + 0) * 4 + j) * 64 + c) * NPIX + p], v);
        v = __fmaf_rn(m[1], g_convn[((long)((b * 4 + 1) * 4 + j) * 64 + c) * NPIX + p], v);
        v = __fmaf_rn(m[2], g_convn[((long)((b * 4 + 2) * 4 + j) * 64 + c) * NPIX + p], v);
        v = __fmaf_rn(m[3], g_convn[((long)((b * 4 + 3) * 4 + j) * 64 + c) * NPIX + p], v);
        g_agg[((long)bj * 64 + c) * NPIX + p] = __fmul_rn(0.25f, v);
    }
}

// ======== tiled direct 3x3 conv (SAME), NCHW fp32, FFMA2 ========
// 16x8 tile, 128 thr, 4 blocks/SM. Uniform plain-LDG staging (two sources).
// Inner loop identical to R10: 288 FFMA2 : ~108 other per ci-slice per thread.
// MODE 0: z<32 -> NBR (src=g_nbr, mask skip, out=convn)
//         z>=32 -> EGO (src=ysrc, +msg_b, out=ego)
// MODE 2: GRU: ci<64 from ysrc, ci>=64 from g_agg; (upd,cand) lanes;
//         epilogue sigmoid*tanh -> ydst
template <int MODE, int CIN>
__global__ __launch_bounds__(128, 4)
void conv_all(const float* __restrict__ ysrc,
              const float* __restrict__ nbr,
              const float* __restrict__ agg,
              const float2* __restrict__ Wnbr,
              const float2* __restrict__ Wego,
              const float* __restrict__ msgb,
              const float2* __restrict__ bgru2,
              float* __restrict__ convn_out,
              float* __restrict__ ego_out,
              float* __restrict__ ydst) {
    __shared__ float sX[8][10][20];          // 8ci x 10 halo rows x 18(+2)
    __shared__ float2 sW2[32 * 72];          // 32 pairs x 8 ci x 9 taps

    const int z = blockIdx.z;
    const bool isNbr = (MODE == 0) && (z < 32);
    const int img = (MODE == 0) ? (isNbr ? z : z - 32) : z;
    const int tx = blockIdx.x % 5, ty = blockIdx.x / 5;
    const int w0 = tx * 16, h0 = ty * 8;
    const int t = threadIdx.x;
    const int s = t & 31;
    const int wl = s & 15;           // col in tile
    const int hq = s >> 4;           // 0..1 -> rows hq*4..hq*4+3
    const int cg = t >> 5;           // 0..3 cout group (8 pairs each)

    const float* srcA;               // ci < splitC
    const float* srcB;               // ci >= splitC
    int splitC;
    const float2* Wt2;
    if (MODE == 0) {
        if (isNbr) {
            const float* mp = g_mask + (long)img * NPIX;
            int any = (mp[(h0 + (t >> 4)) * HW + (w0 + (t & 15))] != 0.0f);
            if (__syncthreads_count(any) == 0) return;
            srcA = nbr + (long)img * 64 * NPIX;
            Wt2 = Wnbr;
        } else {
            srcA = ysrc + (long)img * 64 * NPIX;
            Wt2 = Wego;
        }
        srcB = srcA;
        splitC = 64;
    } else {
        srcA = ysrc + (long)img * 64 * NPIX;
        srcB = agg + (long)img * 64 * NPIX;
        splitC = 64;
        Wt2 = Wnbr;                  // carries gru weights in MODE2 call
    }

    ull acc2[4][8];
#pragma unroll
    for (int k = 0; k < 4; k++)
#pragma unroll
        for (int j = 0; j < 8; j++) acc2[k][j] = 0ULL;

    for (int cin0 = 0; cin0 < CIN; cin0 += 8) {
        const float* src = (cin0 < splitC) ? srcA : srcB;
        int cbase = (cin0 < splitC) ? cin0 : cin0 - splitC;
        // ---- stage input: 8ci x 10 x 18, plain coalesced LDG ----
        for (int idx = t; idx < 8 * 180; idx += 128) {
            int ci = idx / 180, rem = idx % 180;
            int r = rem / 18, c = rem % 18;
            int gh = h0 - 1 + r, gw = w0 - 1 + c;
            float v = 0.0f;
            if (gh >= 0 && gh < HW && gw >= 0 && gw < HW)
                v = src[(cbase + ci) * NPIX + gh * HW + gw];
            sX[ci][r][c] = v;
        }
        // ---- stage weights: 32 pairs x 8ci x 9 (float2) ----
        for (int idx = t; idx < 32 * 72; idx += 128) {
            int co2 = idx / 72, rem = idx % 72;
            sW2[co2 * 72 + rem] =
                Wt2[((blockIdx.y * 32 + co2) * CIN + cin0) * 9 + rem];
        }
        __syncthreads();
#pragma unroll 1
        for (int ci = 0; ci < 8; ci++) {
            ull xb[6][3];
#pragma unroll
            for (int rr = 0; rr < 6; rr++)
#pragma unroll
                for (int cc = 0; cc < 3; cc++)
                    xb[rr][cc] = bcast2(sX[ci][hq * 4 + rr][wl + cc]);
            const float2* wp = &sW2[(cg * 8) * 72 + ci * 9];
#pragma unroll
            for (int j = 0; j < 8; j++) {
#pragma unroll
                for (int tap = 0; tap < 9; tap++) {
                    ull w2 = *reinterpret_cast<const ull*>(&wp[j * 72 + tap]);
                    int r = tap / 3, c = tap % 3;
                    fma2(acc2[0][j], xb[0 + r][c], w2);
                    fma2(acc2[1][j], xb[1 + r][c], w2);
                    fma2(acc2[2][j], xb[2 + r][c], w2);
                    fma2(acc2[3][j], xb[3 + r][c], w2);
                }
            }
        }
        __syncthreads();
    }
    // ---- epilogue ----
    if (MODE == 2) {
#pragma unroll
        for (int j = 0; j < 8; j++) {
            int pr = blockIdx.y * 32 + cg * 8 + j;
            float2 bb = bgru2[pr];
#pragma unroll
            for (int k = 0; k < 4; k++) {
                int h = h0 + hq * 4 + k, w = w0 + wl;
                float2 f = unpack2(acc2[k][j]);
                ydst[((long)img * 64 + pr) * NPIX + h * HW + w] =
                    sigmoid_acc(f.x + bb.x) * tanh_acc(f.y + bb.y);
            }
        }
    } else {
        float* outp = isNbr ? (convn_out + (long)img * 64 * NPIX)
                            : (ego_out + (long)img * 64 * NPIX);
#pragma unroll
        for (int j = 0; j < 8; j++) {
            int co = (cg * 8 + j) * 2;
            float bv0 = isNbr ? 0.0f : msgb[co];
            float bv1 = isNbr ? 0.0f : msgb[co + 1];
#pragma unroll
            for (int k = 0; k < 4; k++) {
                int h = h0 + hq * 4 + k, w = w0 + wl;
                float2 f = unpack2(acc2[k][j]);
                outp[(long)co * NPIX + h * HW + w] = f.x + bv0;
                outp[(long)(co + 1) * NPIX + h * HW + w] = f.y + bv1;
            }
        }
    }
}

// ---------------- weight prepack ----------------
__global__ void k_prepack(const float* __restrict__ msg_w,
                          const float* __restrict__ gates_w,
                          const float* __restrict__ gates_b,
                          const float* __restrict__ can_w,
                          const float* __restrict__ can_b) {
    int idx = blockIdx.x * 256 + threadIdx.x;
    if (idx < 18432) {                         // msg split: [co2][ci<64][9]
        int co2 = idx / 576, rem = idx % 576;
        int coA = 2 * co2, coB = 2 * co2 + 1;
        g_wnbr2[idx] = make_float2(msg_w[coA * 1152 + rem],
                                   msg_w[coB * 1152 + rem]);
        g_wego2[idx] = make_float2(msg_w[coA * 1152 + 576 + rem],
                                   msg_w[coB * 1152 + 576 + rem]);
        return;
    }
    int k = idx - 18432;
    if (k < 73728) {                           // gru (update,cand) lane pairs
        int pr = k / 1152, rem = k % 1152;
        g_wgru2[k] = make_float2(gates_w[(64 + pr) * 1728 + rem],
                                 can_w[pr * 1728 + rem]);
        return;
    }
    k -= 73728;
    if (k < 64)
        g_bgru2[k] = make_float2(gates_b[64 + k], can_b[k]);
}

// ---------------- output: out[b,h,w,o] = mlp_w[o,:]·h1[b,0,:,w,79-h]+mlp_b ----
__global__ void k_out(const float* __restrict__ mlp_w,
                      const float* __restrict__ mlp_b,
                      const float* __restrict__ yfin,
                      float* __restrict__ out) {
    __shared__ float sW[64 * 65];
    __shared__ float sx[4][64];
    int t = threadIdx.x;
    for (int idx = t; idx < 4096; idx += 256) {
        int o = idx >> 6, c = idx & 63;
        sW[c * 65 + o] = mlp_w[idx];
    }
    int pix = t >> 6, o = t & 63;
    int pp = blockIdx.x * 4 + pix;
    int b = pp / NPIX, pr = pp % NPIX;
    int h = pr / HW, w = pr % HW;
    int q = w * HW + (HW - 1 - h);
    sx[pix][o] = yfin[(b * 4) * 64 * NPIX + o * NPIX + q];
    __syncthreads();
    float acc = mlp_b[o];
#pragma unroll 8
    for (int c = 0; c < 64; c++)
        acc = fmaf(sx[pix][c], sW[c * 65 + o], acc);
    out[pp * 64 + o] = acc;
}

// ---------------- host orchestration ----------------
extern "C" void kernel_launch(void* const* d_in, const int* in_sizes, int n_in,
                              void* d_out, int out_size) {
    const float* x       = (const float*)d_in[0];
    const float* pt      = (const float*)d_in[2];
    const float* msg_w   = (const float*)d_in[4];
    const float* msg_b   = (const float*)d_in[5];
    const float* gates_w = (const float*)d_in[6];
    const float* gates_b = (const float*)d_in[7];
    const float* can_w   = (const float*)d_in[8];
    const float* can_b   = (const float*)d_in[9];
    const float* mlp_w   = (const float*)d_in[10];
    const float* mlp_b   = (const float*)d_in[11];

    float *p_y, *p_y2, *p_nbr, *p_convn, *p_ego, *p_agg;
    float2 *p_wnbr2, *p_wego2, *p_wgru2, *p_bgru2;
    cudaGetSymbolAddress((void**)&p_y, g_y);
    cudaGetSymbolAddress((void**)&p_y2, g_y2);
    cudaGetSymbolAddress((void**)&p_nbr, g_nbr);
    cudaGetSymbolAddress((void**)&p_convn, g_convn);
    cudaGetSymbolAddress((void**)&p_ego, g_ego);
    cudaGetSymbolAddress((void**)&p_agg, g_agg);
    cudaGetSymbolAddress((void**)&p_wnbr2, g_wnbr2);
    cudaGetSymbolAddress((void**)&p_wego2, g_wego2);
    cudaGetSymbolAddress((void**)&p_wgru2, g_wgru2);
    cudaGetSymbolAddress((void**)&p_bgru2, g_bgru2);

    k_minv<<<1, 32>>>(pt);
    k_prepack<<<(18432 + 73728 + 64 + 255) / 256, 256>>>(msg_w, gates_w,
                                                         gates_b, can_w, can_b);
    k_maskall<<<dim3(25, NIMG), 256>>>();
    k_transform<<<(NIMG * 64 * NPIX) / 256, 256>>>(x);

    for (int it = 0; it < 2; it++) {
        const float* ysrc = (it == 0) ? p_y : p_y2;
        float* ydst       = (it == 0) ? p_y2 : p_y;
        // bilinear warp (HBM-bound, frees conv issue slots)
        k_warp<<<dim3(25, NPAIR), 256>>>(ysrc);
        // merged NBR(32) + EGO(8): 2000 blocks of 128 thr, plain staging
        conv_all<0, 64><<<dim3(50, 1, 40), 128>>>(
            ysrc, p_nbr, nullptr, p_wnbr2, p_wego2, msg_b, nullptr,
            p_convn, p_ego, nullptr);
        // masked mean (HBM-bound)
        k_agg<<<dim3(25, NIMG), 256>>>();
        // GRU conv + fused pointwise: 800 blocks of 128 thr
        conv_all<2, 128><<<dim3(50, 2, NIMG), 128>>>(
            ysrc, nullptr, p_agg, p_wgru2, nullptr, nullptr, p_bgru2,
            nullptr, nullptr, ydst);
    }

    k_out<<<2 * NPIX / 4, 256>>>(mlp_w, mlp_b, p_y, (float*)d_out);
}

// round 13
// speedup vs baseline: 1.1347x; 1.0675x over previous
#include <cuda_runtime.h>
#include <math.h>

#define HW    80
#define NPIX  6400          // 80*80
#define NPAIR 32            // B*L*L
#define NIMG  8             // B*L

typedef unsigned long long ull;

// ---------------- scratch (static __device__, no allocations) ----------------
__device__ float g_minv[NPAIR * 6];
__device__ float g_mask[NPAIR * NPIX];
__device__ float g_masksum[NIMG * NPIX];
__device__ float g_y[NIMG * 64 * NPIX];        // ping
__device__ float g_y2[NIMG * 64 * NPIX];       // pong
__device__ float g_nbr[NPAIR * 64 * NPIX];     // warped neighbors
__device__ float g_convn[NPAIR * 64 * NPIX];   // conv(neighbor)
__device__ float g_ego[NIMG * 64 * NPIX];      // conv(ego)+bias
__device__ float g_agg[NIMG * 64 * NPIX];      // masked mean
// slice-major weight layouts: [slice][couty][co2][ci8][tap9]
__device__ float2 g_wnbr2[8 * 32 * 72];        // CIN=64: 8 slices
__device__ float2 g_wego2[8 * 32 * 72];
__device__ float2 g_wgru2[16 * 2 * 32 * 72];   // CIN=128: 16 slices x 2 couty
__device__ float2 g_bgru2[64];                 // (gates_b[64+j], can_b[j])

// ---------------- packed fp32x2 helpers (sm_103a FFMA2) ----------------
__device__ __forceinline__ void fma2(ull& d, ull a, ull b) {
    asm("fma.rn.f32x2 %0, %1, %2, %0;" : "+l"(d) : "l"(a), "l"(b));
}
__device__ __forceinline__ ull bcast2(float v) {
    ull r;
    asm("mov.b64 %0, {%1, %1};" : "=l"(r) : "f"(v));
    return r;
}
__device__ __forceinline__ float2 unpack2(ull v) {
    float2 f;
    asm("mov.b64 {%0, %1}, %2;" : "=f"(f.x), "=f"(f.y) : "l"(v));
    return f;
}

// accurate activations (avoid fast-math tanh.approx)
__device__ __forceinline__ float sigmoid_acc(float u) {
    return 1.0f / (1.0f + expf(-u));
}
__device__ __forceinline__ float tanh_acc(float x) {
    float a = fabsf(x);
    float e = expf(-2.0f * a);
    float t = (1.0f - e) / (1.0f + e);
    return copysignf(t, x);
}

// ---------------- affine inverse: replicate reference fp32 arithmetic -------
__global__ void k_minv(const float* __restrict__ P) {
    int p = threadIdx.x;
    if (p >= NPAIR) return;
    const float* M = P + p * 16;
    float a = M[0], b = M[1];
    float c = M[4], d = M[5];
    float txs = __fdiv_rn(M[3], 0.8f);
    float tys = __fdiv_rn(M[7], 0.8f);
    const float cx = 40.0f, cy = 40.0f;
    float dot0 = __fadd_rn(__fmul_rn(a, cx), __fmul_rn(b, cy));
    float dot1 = __fadd_rn(__fmul_rn(c, cx), __fmul_rn(d, cy));
    float Tx = __fadd_rn(__fsub_rn(cx, dot0), txs);
    float Ty = __fadd_rn(__fsub_rn(cy, dot1), tys);

    float ra  = __fdiv_rn(1.0f, a);
    float l10 = __fmul_rn(c, ra);
    float u22 = __fmaf_rn(-l10, b, d);
    float u23 = __fmaf_rn(-l10, Tx, Ty);

    float x1_0 = __fdiv_rn(-l10, u22);
    float x0_0 = __fdiv_rn(__fmaf_rn(-b, x1_0, 1.0f), a);
    float x1_1 = __fdiv_rn(1.0f, u22);
    float x0_1 = __fdiv_rn(__fmul_rn(-b, x1_1), a);
    float x1_2 = __fdiv_rn(-u23, u22);
    float x0_2 = __fdiv_rn(__fmaf_rn(-b, x1_2, -Tx), a);

    float* o = g_minv + p * 6;
    o[0] = x0_0; o[1] = x0_1; o[2] = x0_2;
    o[3] = x1_0; o[4] = x1_1; o[5] = x1_2;
}

__device__ __forceinline__ float coordx(const float* mv, float x, float y) {
    float s = __fmul_rn(mv[0], x);
    s = __fmaf_rn(mv[1], y, s);
    return __fadd_rn(s, mv[2]);
}
__device__ __forceinline__ float coordy(const float* mv, float x, float y) {
    float s = __fmul_rn(mv[3], x);
    s = __fmaf_rn(mv[4], y, s);
    return __fadd_rn(s, mv[5]);
}

// ---------------- masks + masksum fused ----------------
__global__ void k_maskall() {
    int bj = blockIdx.y;                 // b*4 + j
    int p = blockIdx.x * 256 + threadIdx.x;
    if (p >= NPIX) return;
    int b = bj >> 2, j = bj & 3;
    float x = (float)(p % HW), y = (float)(p / HW);
    float s = 0.0f;
#pragma unroll
    for (int i = 0; i < 4; i++) {
        int pair = (b * 4 + i) * 4 + j;
        const float* mv = g_minv + pair * 6;
        float sx = coordx(mv, x, y);
        float sy = coordy(mv, x, y);
        int ix = (int)rintf(sx);
        int iy = (int)rintf(sy);
        float m = (ix >= 0 && ix < HW && iy >= 0 && iy < HW) ? 1.0f : 0.0f;
        g_mask[pair * NPIX + p] = m;
        s += m;
    }
    g_masksum[bj * NPIX + p] = s;
}

// ---------------- initial transform: y[c,h,w] = x[c, 79-w, h] ----------------
__global__ void k_transform(const float* __restrict__ x) {
    int idx = blockIdx.x * 256 + threadIdx.x;
    int p = idx % NPIX;
    int c = (idx / NPIX) & 63;
    int bl = idx / (NPIX * 64);
    int h = p / HW, w = p % HW;
    g_y[idx] = x[(bl * 64 + c) * NPIX + (HW - 1 - w) * HW + h];
}

// ---------------- bilinear warp of y[b,i] by T[pair] (HBM-bound) ------------
__global__ void k_warp(const float* __restrict__ ysrc) {
    int pair = blockIdx.y;
    int p = blockIdx.x * 256 + threadIdx.x;
    if (p >= NPIX) return;
    int b = pair >> 4;
    int i = (pair >> 2) & 3;
    const float* mv = g_minv + pair * 6;
    float x = (float)(p % HW), y = (float)(p / HW);
    float sx = coordx(mv, x, y);
    float sy = coordy(mv, x, y);
    float x0f = floorf(sx), y0f = floorf(sy);
    float fx = __fsub_rn(sx, x0f), fy = __fsub_rn(sy, y0f);
    int x0 = (int)x0f, y0 = (int)y0f;
    int x1 = x0 + 1, y1 = y0 + 1;
    int cx0 = min(max(x0, 0), HW - 1), cx1 = min(max(x1, 0), HW - 1);
    int cy0 = min(max(y0, 0), HW - 1), cy1 = min(max(y1, 0), HW - 1);
    float vx0 = (x0 >= 0 && x0 < HW) ? 1.0f : 0.0f;
    float vx1 = (x1 >= 0 && x1 < HW) ? 1.0f : 0.0f;
    float vy0 = (y0 >= 0 && y0 < HW) ? 1.0f : 0.0f;
    float vy1 = (y1 >= 0 && y1 < HW) ? 1.0f : 0.0f;
    float gx = __fsub_rn(1.0f, fx), gy = __fsub_rn(1.0f, fy);
    float w00 = __fmul_rn(__fmul_rn(vx0, vy0), __fmul_rn(gx, gy));
    float w10 = __fmul_rn(__fmul_rn(vx1, vy0), __fmul_rn(fx, gy));
    float w01 = __fmul_rn(__fmul_rn(vx0, vy1), __fmul_rn(gx, fy));
    float w11 = __fmul_rn(__fmul_rn(vx1, vy1), __fmul_rn(fx, fy));
    int i00 = cy0 * HW + cx0, i10 = cy0 * HW + cx1;
    int i01 = cy1 * HW + cx0, i11 = cy1 * HW + cx1;
    const float* src = ysrc + (long)(b * 4 + i) * 64 * NPIX;
    float* dst = g_nbr + (long)pair * 64 * NPIX;
#pragma unroll 4
    for (int c = 0; c < 64; c++) {
        const float* sc = src + c * NPIX;
        float v = __fmul_rn(w00, sc[i00]);
        v = __fadd_rn(v, __fmul_rn(w10, sc[i10]));
        v = __fadd_rn(v, __fmul_rn(w01, sc[i01]));
        v = __fadd_rn(v, __fmul_rn(w11, sc[i11]));
        dst[c * NPIX + p] = v;
    }
}

// ---------------- masked mean over i (HBM-bound) ----------------
__global__ void k_agg() {
    int bj = blockIdx.y;
    int p = blockIdx.x * 256 + threadIdx.x;
    if (p >= NPIX) return;
    int b = bj >> 2, j = bj & 3;
    float ms = g_masksum[bj * NPIX + p];
    float m[4];
#pragma unroll
    for (int i = 0; i < 4; i++)
        m[i] = g_mask[((b * 4 + i) * 4 + j) * NPIX + p];
#pragma unroll 4
    for (int c = 0; c < 64; c++) {
        float v = __fmul_rn(ms, g_ego[((long)bj * 64 + c) * NPIX + p]);
        v = __fmaf_rn(m[0], g_convn[((long)((b * 4 + 0) * 4 + j) * 64 + c) * NPIX + p], v);
        v = __fmaf_rn(m[1], g_convn[((long)((b * 4 + 1) * 4 + j) * 64 + c) * NPIX + p], v);
        v = __fmaf_rn(m[2], g_convn[((long)((b * 4 + 2) * 4 + j) * 64 + c) * NPIX + p], v);
        v = __fmaf_rn(m[3], g_convn[((long)((b * 4 + 3) * 4 + j) * 64 + c) * NPIX + p], v);
        g_agg[((long)bj * 64 + c) * NPIX + p] = __fmul_rn(0.25f, v);
    }
}

// ======== tiled direct 3x3 conv (SAME), NCHW fp32, FFMA2 ========
// 16x8 tile, 128 thr, 4 blocks/SM. Staging with minimal index math:
//  - inputs: thread owns ci = t>>4, 12 fixed items (k*16 + sub), interior
//    fast path without bounds predicates
//  - weights: slice-major gmem layout -> flat strided copy, no div/mod
// Inner FFMA2 loop identical to R12 (bit-identical arithmetic).
template <int MODE, int CIN>
__global__ __launch_bounds__(128, 4)
void conv_all(const float* __restrict__ ysrc,
              const float* __restrict__ nbr,
              const float* __restrict__ agg,
              const float2* __restrict__ Wnbr,
              const float2* __restrict__ Wego,
              const float* __restrict__ msgb,
              const float2* __restrict__ bgru2,
              float* __restrict__ convn_out,
              float* __restrict__ ego_out,
              float* __restrict__ ydst) {
    __shared__ float sX[8][10][20];          // 8ci x 10 halo rows x 18(+2)
    __shared__ float2 sW2[32 * 72];          // 32 pairs x 8 ci x 9 taps

    const int z = blockIdx.z;
    const bool isNbr = (MODE == 0) && (z < 32);
    const int img = (MODE == 0) ? (isNbr ? z : z - 32) : z;
    const int couty = blockIdx.y;
    const int tx = blockIdx.x % 5, ty = blockIdx.x / 5;
    const int w0 = tx * 16, h0 = ty * 8;
    const int t = threadIdx.x;
    const int s = t & 31;
    const int wl = s & 15;           // col in tile
    const int hq = s >> 4;           // 0..1 -> rows hq*4..hq*4+3
    const int cg = t >> 5;           // 0..3 cout group (8 pairs each)
    // staging identity
    const int ciS = t >> 4;          // owned ci 0..7
    const int sub = t & 15;
    const bool interior = (tx >= 1 && tx <= 3 && ty >= 1 && ty <= 8);

    const float* srcA;               // slices < CIN/2... (MODE2: first 8)
    const float* srcB;
    const float2* Wt2;
    int wstride;                     // couty slabs per slice in weight layout
    if (MODE == 0) {
        if (isNbr) {
            const float* mp = g_mask + (long)img * NPIX;
            int any = (mp[(h0 + (t >> 4)) * HW + (w0 + (t & 15))] != 0.0f);
            if (__syncthreads_count(any) == 0) return;
            srcA = nbr + (long)img * 64 * NPIX;
            Wt2 = Wnbr;
        } else {
            srcA = ysrc + (long)img * 64 * NPIX;
            Wt2 = Wego;
        }
        srcB = srcA;
        wstride = 1;
    } else {
        srcA = ysrc + (long)img * 64 * NPIX;
        srcB = agg + (long)img * 64 * NPIX;
        Wt2 = Wnbr;                  // carries gru weights in MODE2 call
        wstride = 2;
    }

    ull acc2[4][8];
#pragma unroll
    for (int k = 0; k < 4; k++)
#pragma unroll
        for (int j = 0; j < 8; j++) acc2[k][j] = 0ULL;

    const int NS = CIN / 8;
#pragma unroll 1
    for (int sl = 0; sl < NS; sl++) {
        const float* src = (sl < 8) ? srcA : srcB;
        int cbase = (sl & 7) * 8;
        // ---- stage input: thread owns ci, items k*16+sub over 10x18 ----
        {
            const float* sp = src + (cbase + ciS) * NPIX;
            if (interior) {
                const float* sp0 = sp + (h0 - 1) * HW + (w0 - 1);
#pragma unroll
                for (int k = 0; k < 12; k++) {
                    int item = k * 16 + sub;
                    if (k < 11 || item < 180) {
                        int r = item / 18, c = item - r * 18;
                        sX[ciS][r][c] = sp0[r * HW + c];
                    }
                }
            } else {
#pragma unroll
                for (int k = 0; k < 12; k++) {
                    int item = k * 16 + sub;
                    if (k < 11 || item < 180) {
                        int r = item / 18, c = item - r * 18;
                        int gh = h0 - 1 + r, gw = w0 - 1 + c;
                        float v = 0.0f;
                        if (gh >= 0 && gh < HW && gw >= 0 && gw < HW)
                            v = sp[gh * HW + gw];
                        sX[ciS][r][c] = v;
                    }
                }
            }
        }
        // ---- stage weights: flat copy of slice-major layout (no div) ----
        {
            const float2* wsrc = Wt2 + (long)(sl * wstride + couty) * 2304;
#pragma unroll
            for (int k = 0; k < 18; k++)
                sW2[t + k * 128] = wsrc[t + k * 128];
        }
        __syncthreads();
#pragma unroll 1
        for (int ci = 0; ci < 8; ci++) {
            ull xb[6][3];
#pragma unroll
            for (int rr = 0; rr < 6; rr++)
#pragma unroll
                for (int cc = 0; cc < 3; cc++)
                    xb[rr][cc] = bcast2(sX[ci][hq * 4 + rr][wl + cc]);
            const float2* wp = &sW2[(cg * 8) * 72 + ci * 9];
#pragma unroll
            for (int j = 0; j < 8; j++) {
#pragma unroll
                for (int tap = 0; tap < 9; tap++) {
                    ull w2 = *reinterpret_cast<const ull*>(&wp[j * 72 + tap]);
                    int r = tap / 3, c = tap % 3;
                    fma2(acc2[0][j], xb[0 + r][c], w2);
                    fma2(acc2[1][j], xb[1 + r][c], w2);
                    fma2(acc2[2][j], xb[2 + r][c], w2);
                    fma2(acc2[3][j], xb[3 + r][c], w2);
                }
            }
        }
        __syncthreads();
    }
    // ---- epilogue ----
    if (MODE == 2) {
#pragma unroll
        for (int j = 0; j < 8; j++) {
            int pr = couty * 32 + cg * 8 + j;
            float2 bb = bgru2[pr];
#pragma unroll
            for (int k = 0; k < 4; k++) {
                int h = h0 + hq * 4 + k, w = w0 + wl;
                float2 f = unpack2(acc2[k][j]);
                ydst[((long)img * 64 + pr) * NPIX + h * HW + w] =
                    sigmoid_acc(f.x + bb.x) * tanh_acc(f.y + bb.y);
            }
        }
    } else {
        float* outp = isNbr ? (convn_out + (long)img * 64 * NPIX)
                            : (ego_out + (long)img * 64 * NPIX);
#pragma unroll
        for (int j = 0; j < 8; j++) {
            int co = (cg * 8 + j) * 2;
            float bv0 = isNbr ? 0.0f : msgb[co];
            float bv1 = isNbr ? 0.0f : msgb[co + 1];
#pragma unroll
            for (int k = 0; k < 4; k++) {
                int h = h0 + hq * 4 + k, w = w0 + wl;
                float2 f = unpack2(acc2[k][j]);
                outp[(long)co * NPIX + h * HW + w] = f.x + bv0;
                outp[(long)(co + 1) * NPIX + h * HW + w] = f.y + bv1;
            }
        }
    }
}

// ---------------- weight prepack (slice-major layouts) ----------------
__global__ void k_prepack(const float* __restrict__ msg_w,
                          const float* __restrict__ gates_w,
                          const float* __restrict__ gates_b,
                          const float* __restrict__ can_w,
                          const float* __restrict__ can_b) {
    int idx = blockIdx.x * 256 + threadIdx.x;
    if (idx < 18432) {       // msg: [slice8][co2 32][ci8][tap9]
        int tap = idx % 9;
        int tmp = idx / 9;
        int ci = tmp & 7;  tmp >>= 3;
        int co2 = tmp & 31;
        int slice = tmp >> 5;
        int cin = slice * 8 + ci;
        int coA = 2 * co2, coB = 2 * co2 + 1;
        int r = cin * 9 + tap;
        g_wnbr2[idx] = make_float2(msg_w[coA * 1152 + r],
                                   msg_w[coB * 1152 + r]);
        g_wego2[idx] = make_float2(msg_w[coA * 1152 + 576 + r],
                                   msg_w[coB * 1152 + 576 + r]);
        return;
    }
    int k = idx - 18432;
    if (k < 73728) {         // gru: [slice16][couty2][co2 32][ci8][tap9]
        int tap = k % 9;
        int tmp = k / 9;
        int ci = tmp & 7;  tmp >>= 3;
        int co2 = tmp & 31; tmp >>= 5;
        int couty = tmp & 1;
        int slice = tmp >> 1;
        int cin = slice * 8 + ci;
        int pr = couty * 32 + co2;
        int r = cin * 9 + tap;
        g_wgru2[k] = make_float2(gates_w[(64 + pr) * 1728 + r],
                                 can_w[pr * 1728 + r]);
        return;
    }
    k -= 73728;
    if (k < 64)
        g_bgru2[k] = make_float2(gates_b[64 + k], can_b[k]);
}

// ---------------- output: out[b,h,w,o] = mlp_w[o,:]·h1[b,0,:,w,79-h]+mlp_b ----
__global__ void k_out(const float* __restrict__ mlp_w,
                      const float* __restrict__ mlp_b,
                      const float* __restrict__ yfin,
                      float* __restrict__ out) {
    __shared__ float sW[64 * 65];
    __shared__ float sx[4][64];
    int t = threadIdx.x;
    for (int idx = t; idx < 4096; idx += 256) {
        int o = idx >> 6, c = idx & 63;
        sW[c * 65 + o] = mlp_w[idx];
    }
    int pix = t >> 6, o = t & 63;
    int pp = blockIdx.x * 4 + pix;
    int b = pp / NPIX, pr = pp % NPIX;
    int h = pr / HW, w = pr % HW;
    int q = w * HW + (HW - 1 - h);
    sx[pix][o] = yfin[(b * 4) * 64 * NPIX + o * NPIX + q];
    __syncthreads();
    float acc = mlp_b[o];
#pragma unroll 8
    for (int c = 0; c < 64; c++)
        acc = fmaf(sx[pix][c], sW[c * 65 + o], acc);
    out[pp * 64 + o] = acc;
}

// ---------------- host orchestration ----------------
extern "C" void kernel_launch(void* const* d_in, const int* in_sizes, int n_in,
                              void* d_out, int out_size) {
    const float* x       = (const float*)d_in[0];
    const float* pt      = (const float*)d_in[2];
    const float* msg_w   = (const float*)d_in[4];
    const float* msg_b   = (const float*)d_in[5];
    const float* gates_w = (const float*)d_in[6];
    const float* gates_b = (const float*)d_in[7];
    const float* can_w   = (const float*)d_in[8];
    const float* can_b   = (const float*)d_in[9];
    const float* mlp_w   = (const float*)d_in[10];
    const float* mlp_b   = (const float*)d_in[11];

    float *p_y, *p_y2, *p_nbr, *p_convn, *p_ego, *p_agg;
    float2 *p_wnbr2, *p_wego2, *p_wgru2, *p_bgru2;
    cudaGetSymbolAddress((void**)&p_y, g_y);
    cudaGetSymbolAddress((void**)&p_y2, g_y2);
    cudaGetSymbolAddress((void**)&p_nbr, g_nbr);
    cudaGetSymbolAddress((void**)&p_convn, g_convn);
    cudaGetSymbolAddress((void**)&p_ego, g_ego);
    cudaGetSymbolAddress((void**)&p_agg, g_agg);
    cudaGetSymbolAddress((void**)&p_wnbr2, g_wnbr2);
    cudaGetSymbolAddress((void**)&p_wego2, g_wego2);
    cudaGetSymbolAddress((void**)&p_wgru2, g_wgru2);
    cudaGetSymbolAddress((void**)&p_bgru2, g_bgru2);

    k_minv<<<1, 32>>>(pt);
    k_prepack<<<(18432 + 73728 + 64 + 255) / 256, 256>>>(msg_w, gates_w,
                                                         gates_b, can_w, can_b);
    k_maskall<<<dim3(25, NIMG), 256>>>();
    k_transform<<<(NIMG * 64 * NPIX) / 256, 256>>>(x);

    for (int it = 0; it < 2; it++) {
        const float* ysrc = (it == 0) ? p_y : p_y2;
        float* ydst       = (it == 0) ? p_y2 : p_y;
        // bilinear warp (HBM-bound, frees conv issue slots)
        k_warp<<<dim3(25, NPAIR), 256>>>(ysrc);
        // merged NBR(32) + EGO(8): 2000 blocks of 128 thr
        conv_all<0, 64><<<dim3(50, 1, 40), 128>>>(
            ysrc, p_nbr, nullptr, p_wnbr2, p_wego2, msg_b, nullptr,
            p_convn, p_ego, nullptr);
        // masked mean (HBM-bound)
        k_agg<<<dim3(25, NIMG), 256>>>();
        // GRU conv + fused pointwise: 800 blocks of 128 thr
        conv_all<2, 128><<<dim3(50, 2, NIMG), 128>>>(
            ysrc, nullptr, p_agg, p_wgru2, nullptr, nullptr, p_bgru2,
            nullptr, nullptr, ydst);
    }

    k_out<<<2 * NPIX / 4, 256>>>(mlp_w, mlp_b, p_y, (float*)d_out);
}